// round 11
// baseline (speedup 1.0000x reference)
#include <cuda_runtime.h>
#include <cstdint>

// EquivariantLayerNorm: out = (covar + EPS*I)^{-1/2} @ (x - mean) * weight
// covar = xc @ xc^T / D + EPS*diag(1,2,3),  x: (N, 3, 256) fp32.
//
// R11 = R10 (64-thread blocks, two 16-lane sample groups per warp, cp.async
// staging, 4-level butterfly, closed-form A^{-1/2}, barrier-free, streaming
// stores) with libm acosf replaced by the Abramowitz-Stegun 4-term
// polynomial (|err| <= 6.7e-5 rad; output rel-err ~1e-5 vs 1e-3 tolerance).
// This trims the longest redundant serial chain in the per-lane solve.

__device__ __forceinline__ void cp_async16(unsigned saddr, const void* gptr) {
    asm volatile("cp.async.cg.shared.global [%0], [%1], 16;"
                 :: "r"(saddr), "l"(gptr));
}

__device__ __forceinline__ float sum4(float4 a) {
    return (a.x + a.y) + (a.z + a.w);
}
__device__ __forceinline__ float dot4(float4 a, float4 b, float acc) {
    acc = fmaf(a.x, b.x, acc);
    acc = fmaf(a.y, b.y, acc);
    acc = fmaf(a.z, b.z, acc);
    acc = fmaf(a.w, b.w, acc);
    return acc;
}

// Abramowitz-Stegun 4.4.45: |err| <= 6.7e-5 rad over [-1,1]
__device__ __forceinline__ float acos_fast(float x) {
    const float ax = fabsf(x);
    float p = fmaf(ax, -0.0187293f, 0.0742610f);
    p = fmaf(ax, p, -0.2121144f);
    p = fmaf(ax, p,  1.5707288f);
    const float r = sqrtf(1.0f - ax) * p;
    return (x < 0.0f) ? (3.14159265f - r) : r;
}

__global__ void __launch_bounds__(64, 18) eqln_kernel(
    const float* __restrict__ in,
    const float* __restrict__ weight,
    float* __restrict__ out,
    int nSamples)
{
    __shared__ float smx[2][2][768];   // [warp][half-warp group][elements]

    const int warp = threadIdx.x >> 5;   // 0..1
    const int lane = threadIdx.x & 31;
    const int half = lane >> 4;          // sample group within warp
    const int hl   = lane & 15;          // lane within 16-lane group

    long sample = (long)blockIdx.x * 4 + warp * 2 + half;
    const bool valid = (sample < (long)nSamples);
    long ls = valid ? sample : (long)nSamples - 1;   // clamp for safe load

    // ---- stage this group's sample into smem (bypasses RF) ----
    const char* gsrc = (const char*)(in + ls * 768);
    unsigned sbase = (unsigned)__cvta_generic_to_shared(&smx[warp][half][0]);
    #pragma unroll
    for (int c = 0; c < 12; c++) {
        int f4 = c * 16 + hl;                         // float4 idx 0..191
        cp_async16(sbase + f4 * 16, gsrc + (size_t)f4 * 16);
    }
    asm volatile("cp.async.commit_group;");
    asm volatile("cp.async.wait_group 0;" ::: "memory");
    // each lane reads only the float4s it copied itself -> no sync needed

    // ---- 9-quantity reduction (row sums + raw second moments) ----
    const float4* sx = (const float4*)&smx[warp][half][0];
    float s[9];
    #pragma unroll
    for (int q = 0; q < 9; q++) s[q] = 0.0f;

    #pragma unroll
    for (int c = 0; c < 4; c++) {
        float4 a = sx[       c * 16 + hl];
        float4 b = sx[ 64 +  c * 16 + hl];
        float4 d = sx[128 +  c * 16 + hl];
        s[0] += sum4(a);
        s[1] += sum4(b);
        s[2] += sum4(d);
        s[3] = dot4(a, a, s[3]);
        s[4] = dot4(a, b, s[4]);
        s[5] = dot4(a, d, s[5]);
        s[6] = dot4(b, b, s[6]);
        s[7] = dot4(b, d, s[7]);
        s[8] = dot4(d, d, s[8]);
    }

    // 4-level butterfly within each 16-lane half: both samples reduced at once
    #pragma unroll
    for (int q = 0; q < 9; q++) {
        #pragma unroll
        for (int o = 8; o > 0; o >>= 1)
            s[q] += __shfl_xor_sync(0xffffffffu, s[q], o);
    }

    // ---- closed-form A^{-1/2} (redundant across the 16 lanes of each half) ----
    const float invD = 1.0f / 256.0f;
    const float m0 = s[0] * invD, m1 = s[1] * invD, m2 = s[2] * invD;

    // A = covar + EPS*diag(1,2,3) + EPS*I   (the +EPS*I from 1/sqrt(s+eps))
    const float a00 = fmaf(s[3], invD, -m0 * m0) + 2.0e-3f;
    const float a01 = fmaf(s[4], invD, -m0 * m1);
    const float a02 = fmaf(s[5], invD, -m0 * m2);
    const float a11 = fmaf(s[6], invD, -m1 * m1) + 3.0e-3f;
    const float a12 = fmaf(s[7], invD, -m1 * m2);
    const float a22 = fmaf(s[8], invD, -m2 * m2) + 4.0e-3f;

    // eigenvalues (trigonometric method); A >= 2e-3 I so all roots positive
    const float qm  = (a00 + a11 + a22) * (1.0f / 3.0f);
    const float d0 = a00 - qm, d1 = a11 - qm, d2 = a22 - qm;
    const float off2 = a01*a01 + a02*a02 + a12*a12;
    float p2 = (d0*d0 + d1*d1 + d2*d2) * (1.0f / 6.0f) + off2 * (1.0f / 3.0f);
    p2 = fmaxf(p2, 1.0e-24f);
    const float detB = d0 * (d1*d2 - a12*a12)
                     - a01 * (a01*d2 - a12*a02)
                     + a02 * (a01*a12 - d1*a02);
    const float ip  = rsqrtf(p2);            // 1/p
    float r = 0.5f * detB * (ip * ip * ip);
    r = fminf(fmaxf(r, -1.0f), 1.0f);
    const float phi = acos_fast(r) * (1.0f / 3.0f);
    const float twop = 2.0f * p2 * ip;       // 2p
    const float l1 = qm + twop * __cosf(phi);                 // largest
    const float l3 = qm + twop * __cosf(phi + 2.0943951f);    // smallest
    const float l2 = 3.0f * qm - l1 - l3;

    // cancellation-free divided differences of f(x)=1/sqrt(x)
    const float u = sqrtf(l1), v = sqrtf(l2), w = sqrtf(l3);
    const float uv = u + v, vw = v + w, uw = u + w;
    const float rden = 1.0f / ((u * v * w) * uv * vw * uw);
    const float c2 = (u + v + w) * rden;
    const float c1 = -(w * vw * uw) * rden;
    const float c0 = (v * w) * (vw * uv * uw) * rden;   // = 1/u

    // S = c0*I + c1*(A-l1 I) + c2*(A-l1 I)(A-l2 I)
    const float e0 = a00 - l1, e1 = a11 - l1, e2 = a22 - l1;
    const float g0 = a00 - l2, g1 = a11 - l2, g2 = a22 - l2;
    const float P00 = e0*g0 + a01*a01 + a02*a02;
    const float P01 = a01*(e0 + g1) + a02*a12;
    const float P02 = a02*(e0 + g2) + a01*a12;
    const float P11 = a01*a01 + e1*g1 + a12*a12;
    const float P12 = a12*(e1 + g2) + a01*a02;
    const float P22 = a02*a02 + a12*a12 + e2*g2;

    const float S00 = fmaf(c2, P00, fmaf(c1, e0, c0));
    const float S01 = fmaf(c2, P01, c1 * a01);
    const float S02 = fmaf(c2, P02, c1 * a02);
    const float S11 = fmaf(c2, P11, fmaf(c1, e1, c0));
    const float S12 = fmaf(c2, P12, c1 * a12);
    const float S22 = fmaf(c2, P22, fmaf(c1, e2, c0));

    // bias b = -S*m folds the mean subtraction into the transform
    const float bb0 = -(S00*m0 + S01*m1 + S02*m2);
    const float bb1 = -(S01*m0 + S11*m1 + S12*m2);
    const float bb2 = -(S02*m0 + S12*m1 + S22*m2);

    // ---- epilogue: stream x back from smem, fused transform + weight ----
    if (valid) {
        const float4* __restrict__ w4p = (const float4*)weight;
        float4* __restrict__ xout = (float4*)(out + sample * 768);

        #pragma unroll
        for (int c2i = 0; c2i < 4; c2i++) {
            float4 a = sx[       c2i * 16 + hl];
            float4 b = sx[ 64 +  c2i * 16 + hl];
            float4 d = sx[128 +  c2i * 16 + hl];
            float4 wv = __ldg(&w4p[c2i * 16 + hl]);

            float4 o;
            o.x = fmaf(S00, a.x, fmaf(S01, b.x, fmaf(S02, d.x, bb0))) * wv.x;
            o.y = fmaf(S00, a.y, fmaf(S01, b.y, fmaf(S02, d.y, bb0))) * wv.y;
            o.z = fmaf(S00, a.z, fmaf(S01, b.z, fmaf(S02, d.z, bb0))) * wv.z;
            o.w = fmaf(S00, a.w, fmaf(S01, b.w, fmaf(S02, d.w, bb0))) * wv.w;
            __stcs(&xout[       c2i * 16 + hl], o);

            o.x = fmaf(S01, a.x, fmaf(S11, b.x, fmaf(S12, d.x, bb1))) * wv.x;
            o.y = fmaf(S01, a.y, fmaf(S11, b.y, fmaf(S12, d.y, bb1))) * wv.y;
            o.z = fmaf(S01, a.z, fmaf(S11, b.z, fmaf(S12, d.z, bb1))) * wv.z;
            o.w = fmaf(S01, a.w, fmaf(S11, b.w, fmaf(S12, d.w, bb1))) * wv.w;
            __stcs(&xout[ 64 +  c2i * 16 + hl], o);

            o.x = fmaf(S02, a.x, fmaf(S12, b.x, fmaf(S22, d.x, bb2))) * wv.x;
            o.y = fmaf(S02, a.y, fmaf(S12, b.y, fmaf(S22, d.y, bb2))) * wv.y;
            o.z = fmaf(S02, a.z, fmaf(S12, b.z, fmaf(S22, d.z, bb2))) * wv.z;
            o.w = fmaf(S02, a.w, fmaf(S12, b.w, fmaf(S22, d.w, bb2))) * wv.w;
            __stcs(&xout[128 +  c2i * 16 + hl], o);
        }
    }
}

extern "C" void kernel_launch(void* const* d_in, const int* in_sizes, int n_in,
                              void* d_out, int out_size)
{
    const float* in = (const float*)d_in[0];
    const float* w  = (const float*)d_in[1];
    float* out      = (float*)d_out;

    int nSamples = in_sizes[0] / 768;        // N*3*256 elements -> N samples
    int grid = (nSamples + 3) / 4;           // 4 samples per 64-thread block
    eqln_kernel<<<grid, 64>>>(in, w, out, nSamples);
}

// round 12
// speedup vs baseline: 1.0126x; 1.0126x over previous
#include <cuda_runtime.h>
#include <cstdint>

// EquivariantLayerNorm: out = (covar + EPS*I)^{-1/2} @ (x - mean) * weight
// covar = xc @ xc^T / D + EPS*diag(1,2,3),  x: (N, 3, 256) fp32.
//
// R12: fully register-resident datapath (no smem round-trip).
//   Each 16-lane group owns one sample; each lane holds its 12 float4 in
//   registers via __ldcs (evict-first, MLP=12 front-batched LDG.128).
//   Reduction and epilogue both read registers -> removes 12 STS + 24 LDS
//   per lane of MIO traffic and the all-or-nothing cp.async.wait.
//   4-level butterfly, closed-form A^{-1/2} per lane, streaming stores.
//   64-thread blocks; __launch_bounds__(64,12) gives an 85-reg budget.

__device__ __forceinline__ float sum4(float4 a) {
    return (a.x + a.y) + (a.z + a.w);
}
__device__ __forceinline__ float dot4(float4 a, float4 b, float acc) {
    acc = fmaf(a.x, b.x, acc);
    acc = fmaf(a.y, b.y, acc);
    acc = fmaf(a.z, b.z, acc);
    acc = fmaf(a.w, b.w, acc);
    return acc;
}

__global__ void __launch_bounds__(64, 12) eqln_kernel(
    const float* __restrict__ in,
    const float* __restrict__ weight,
    float* __restrict__ out,
    int nSamples)
{
    const int warp = threadIdx.x >> 5;   // 0..1
    const int lane = threadIdx.x & 31;
    const int half = lane >> 4;          // sample group within warp
    const int hl   = lane & 15;          // lane within 16-lane group

    long sample = (long)blockIdx.x * 4 + warp * 2 + half;
    const bool valid = (sample < (long)nSamples);
    long ls = valid ? sample : (long)nSamples - 1;   // clamp for safe load

    // ---- front-batched register loads: 12 independent LDG.128 ----
    const float4* __restrict__ xin = (const float4*)(in + ls * 768);
    float4 x[12];
    #pragma unroll
    for (int c = 0; c < 4; c++) x[c]     = __ldcs(&xin[       c * 16 + hl]);
    #pragma unroll
    for (int c = 0; c < 4; c++) x[4 + c] = __ldcs(&xin[ 64 +  c * 16 + hl]);
    #pragma unroll
    for (int c = 0; c < 4; c++) x[8 + c] = __ldcs(&xin[128 +  c * 16 + hl]);

    // ---- 9-quantity reduction (row sums + raw second moments) ----
    float s[9];
    #pragma unroll
    for (int q = 0; q < 9; q++) s[q] = 0.0f;

    #pragma unroll
    for (int c = 0; c < 4; c++) {
        float4 a = x[c], b = x[4 + c], d = x[8 + c];
        s[0] += sum4(a);
        s[1] += sum4(b);
        s[2] += sum4(d);
        s[3] = dot4(a, a, s[3]);
        s[4] = dot4(a, b, s[4]);
        s[5] = dot4(a, d, s[5]);
        s[6] = dot4(b, b, s[6]);
        s[7] = dot4(b, d, s[7]);
        s[8] = dot4(d, d, s[8]);
    }

    // 4-level butterfly within each 16-lane half (both samples at once)
    #pragma unroll
    for (int q = 0; q < 9; q++) {
        #pragma unroll
        for (int o = 8; o > 0; o >>= 1)
            s[q] += __shfl_xor_sync(0xffffffffu, s[q], o);
    }

    // ---- closed-form A^{-1/2} (redundant across the 16 lanes) ----
    const float invD = 1.0f / 256.0f;
    const float m0 = s[0] * invD, m1 = s[1] * invD, m2 = s[2] * invD;

    // A = covar + EPS*diag(1,2,3) + EPS*I   (the +EPS*I from 1/sqrt(s+eps))
    const float a00 = fmaf(s[3], invD, -m0 * m0) + 2.0e-3f;
    const float a01 = fmaf(s[4], invD, -m0 * m1);
    const float a02 = fmaf(s[5], invD, -m0 * m2);
    const float a11 = fmaf(s[6], invD, -m1 * m1) + 3.0e-3f;
    const float a12 = fmaf(s[7], invD, -m1 * m2);
    const float a22 = fmaf(s[8], invD, -m2 * m2) + 4.0e-3f;

    // eigenvalues (trigonometric method); A >= 2e-3 I so all roots positive
    const float qm  = (a00 + a11 + a22) * (1.0f / 3.0f);
    const float d0 = a00 - qm, d1 = a11 - qm, d2 = a22 - qm;
    const float off2 = a01*a01 + a02*a02 + a12*a12;
    float p2 = (d0*d0 + d1*d1 + d2*d2) * (1.0f / 6.0f) + off2 * (1.0f / 3.0f);
    p2 = fmaxf(p2, 1.0e-24f);
    const float detB = d0 * (d1*d2 - a12*a12)
                     - a01 * (a01*d2 - a12*a02)
                     + a02 * (a01*a12 - d1*a02);
    const float ip  = rsqrtf(p2);            // 1/p
    float r = 0.5f * detB * (ip * ip * ip);
    r = fminf(fmaxf(r, -1.0f), 1.0f);
    const float phi = acosf(r) * (1.0f / 3.0f);
    const float twop = 2.0f * p2 * ip;       // 2p
    const float l1 = qm + twop * __cosf(phi);                 // largest
    const float l3 = qm + twop * __cosf(phi + 2.0943951f);    // smallest
    const float l2 = 3.0f * qm - l1 - l3;

    // cancellation-free divided differences of f(x)=1/sqrt(x)
    const float u = sqrtf(l1), v = sqrtf(l2), w = sqrtf(l3);
    const float uv = u + v, vw = v + w, uw = u + w;
    const float rden = 1.0f / ((u * v * w) * uv * vw * uw);
    const float c2 = (u + v + w) * rden;
    const float c1 = -(w * vw * uw) * rden;
    const float c0 = (v * w) * (vw * uv * uw) * rden;   // = 1/u

    // S = c0*I + c1*(A-l1 I) + c2*(A-l1 I)(A-l2 I)
    const float e0 = a00 - l1, e1 = a11 - l1, e2 = a22 - l1;
    const float g0 = a00 - l2, g1 = a11 - l2, g2 = a22 - l2;
    const float P00 = e0*g0 + a01*a01 + a02*a02;
    const float P01 = a01*(e0 + g1) + a02*a12;
    const float P02 = a02*(e0 + g2) + a01*a12;
    const float P11 = a01*a01 + e1*g1 + a12*a12;
    const float P12 = a12*(e1 + g2) + a01*a02;
    const float P22 = a02*a02 + a12*a12 + e2*g2;

    const float S00 = fmaf(c2, P00, fmaf(c1, e0, c0));
    const float S01 = fmaf(c2, P01, c1 * a01);
    const float S02 = fmaf(c2, P02, c1 * a02);
    const float S11 = fmaf(c2, P11, fmaf(c1, e1, c0));
    const float S12 = fmaf(c2, P12, c1 * a12);
    const float S22 = fmaf(c2, P22, fmaf(c1, e2, c0));

    // bias b = -S*m folds the mean subtraction into the transform
    const float bb0 = -(S00*m0 + S01*m1 + S02*m2);
    const float bb1 = -(S01*m0 + S11*m1 + S12*m2);
    const float bb2 = -(S02*m0 + S12*m1 + S22*m2);

    // ---- epilogue: transform from registers + weight, streaming stores ----
    if (valid) {
        const float4* __restrict__ w4p = (const float4*)weight;
        float4* __restrict__ xout = (float4*)(out + sample * 768);

        #pragma unroll
        for (int c = 0; c < 4; c++) {
            float4 a = x[c], b = x[4 + c], d = x[8 + c];
            float4 wv = __ldg(&w4p[c * 16 + hl]);

            float4 o;
            o.x = fmaf(S00, a.x, fmaf(S01, b.x, fmaf(S02, d.x, bb0))) * wv.x;
            o.y = fmaf(S00, a.y, fmaf(S01, b.y, fmaf(S02, d.y, bb0))) * wv.y;
            o.z = fmaf(S00, a.z, fmaf(S01, b.z, fmaf(S02, d.z, bb0))) * wv.z;
            o.w = fmaf(S00, a.w, fmaf(S01, b.w, fmaf(S02, d.w, bb0))) * wv.w;
            __stcs(&xout[       c * 16 + hl], o);

            o.x = fmaf(S01, a.x, fmaf(S11, b.x, fmaf(S12, d.x, bb1))) * wv.x;
            o.y = fmaf(S01, a.y, fmaf(S11, b.y, fmaf(S12, d.y, bb1))) * wv.y;
            o.z = fmaf(S01, a.z, fmaf(S11, b.z, fmaf(S12, d.z, bb1))) * wv.z;
            o.w = fmaf(S01, a.w, fmaf(S11, b.w, fmaf(S12, d.w, bb1))) * wv.w;
            __stcs(&xout[ 64 +  c * 16 + hl], o);

            o.x = fmaf(S02, a.x, fmaf(S12, b.x, fmaf(S22, d.x, bb2))) * wv.x;
            o.y = fmaf(S02, a.y, fmaf(S12, b.y, fmaf(S22, d.y, bb2))) * wv.y;
            o.z = fmaf(S02, a.z, fmaf(S12, b.z, fmaf(S22, d.z, bb2))) * wv.z;
            o.w = fmaf(S02, a.w, fmaf(S12, b.w, fmaf(S22, d.w, bb2))) * wv.w;
            __stcs(&xout[128 +  c * 16 + hl], o);
        }
    }
}

extern "C" void kernel_launch(void* const* d_in, const int* in_sizes, int n_in,
                              void* d_out, int out_size)
{
    const float* in = (const float*)d_in[0];
    const float* w  = (const float*)d_in[1];
    float* out      = (float*)d_out;

    int nSamples = in_sizes[0] / 768;        // N*3*256 elements -> N samples
    int grid = (nSamples + 3) / 4;           // 4 samples per 64-thread block
    eqln_kernel<<<grid, 64>>>(in, w, out, nSamples);
}

// round 13
// speedup vs baseline: 1.0188x; 1.0061x over previous
#include <cuda_runtime.h>
#include <cstdint>

// EquivariantLayerNorm: out = (covar + EPS*I)^{-1/2} @ (x - mean) * weight
// covar = xc @ xc^T / D + EPS*diag(1,2,3),  x: (N, 3, 256) fp32.
//
// R13: warp-per-sample, fully register-resident.
//   Each WARP owns one sample; each lane holds 6 float4 (24 data regs,
//   ~60 total vs R12's 80) -> ~2x resident warps at identical per-sample
//   MLP, and 64-thread blocks carry only 2 samples (minimal drain window).
//   Loads via __ldcs (evict-first), 5-level butterfly, closed-form
//   A^{-1/2} redundant per lane, streaming stores. Barrier-free.

__device__ __forceinline__ float sum4(float4 a) {
    return (a.x + a.y) + (a.z + a.w);
}
__device__ __forceinline__ float dot4(float4 a, float4 b, float acc) {
    acc = fmaf(a.x, b.x, acc);
    acc = fmaf(a.y, b.y, acc);
    acc = fmaf(a.z, b.z, acc);
    acc = fmaf(a.w, b.w, acc);
    return acc;
}

__global__ void __launch_bounds__(64, 16) eqln_kernel(
    const float* __restrict__ in,
    const float* __restrict__ weight,
    float* __restrict__ out,
    int nSamples)
{
    const int warp = threadIdx.x >> 5;   // 0..1
    const int lane = threadIdx.x & 31;

    long sample = (long)blockIdx.x * 2 + warp;
    const bool valid = (sample < (long)nSamples);
    long ls = valid ? sample : (long)nSamples - 1;   // clamp for safe load

    // ---- front-batched register loads: 6 independent LDG.128 per lane ----
    const float4* __restrict__ xin = (const float4*)(in + ls * 768);
    float4 x[6];
    x[0] = __ldcs(&xin[       lane]);
    x[1] = __ldcs(&xin[ 32 +  lane]);
    x[2] = __ldcs(&xin[ 64 +  lane]);
    x[3] = __ldcs(&xin[ 96 +  lane]);
    x[4] = __ldcs(&xin[128 +  lane]);
    x[5] = __ldcs(&xin[160 +  lane]);

    // ---- 9-quantity reduction (row sums + raw second moments) ----
    float s[9];
    s[0] = sum4(x[0]) + sum4(x[1]);
    s[1] = sum4(x[2]) + sum4(x[3]);
    s[2] = sum4(x[4]) + sum4(x[5]);
    s[3] = dot4(x[1], x[1], dot4(x[0], x[0], 0.0f));
    s[4] = dot4(x[1], x[3], dot4(x[0], x[2], 0.0f));
    s[5] = dot4(x[1], x[5], dot4(x[0], x[4], 0.0f));
    s[6] = dot4(x[3], x[3], dot4(x[2], x[2], 0.0f));
    s[7] = dot4(x[3], x[5], dot4(x[2], x[4], 0.0f));
    s[8] = dot4(x[5], x[5], dot4(x[4], x[4], 0.0f));

    // 5-level butterfly: every lane ends with the full sums
    #pragma unroll
    for (int q = 0; q < 9; q++) {
        #pragma unroll
        for (int o = 16; o > 0; o >>= 1)
            s[q] += __shfl_xor_sync(0xffffffffu, s[q], o);
    }

    // ---- closed-form A^{-1/2} (redundant across the 32 lanes) ----
    const float invD = 1.0f / 256.0f;
    const float m0 = s[0] * invD, m1 = s[1] * invD, m2 = s[2] * invD;

    // A = covar + EPS*diag(1,2,3) + EPS*I   (the +EPS*I from 1/sqrt(s+eps))
    const float a00 = fmaf(s[3], invD, -m0 * m0) + 2.0e-3f;
    const float a01 = fmaf(s[4], invD, -m0 * m1);
    const float a02 = fmaf(s[5], invD, -m0 * m2);
    const float a11 = fmaf(s[6], invD, -m1 * m1) + 3.0e-3f;
    const float a12 = fmaf(s[7], invD, -m1 * m2);
    const float a22 = fmaf(s[8], invD, -m2 * m2) + 4.0e-3f;

    // eigenvalues (trigonometric method); A >= 2e-3 I so all roots positive
    const float qm  = (a00 + a11 + a22) * (1.0f / 3.0f);
    const float d0 = a00 - qm, d1 = a11 - qm, d2 = a22 - qm;
    const float off2 = a01*a01 + a02*a02 + a12*a12;
    float p2 = (d0*d0 + d1*d1 + d2*d2) * (1.0f / 6.0f) + off2 * (1.0f / 3.0f);
    p2 = fmaxf(p2, 1.0e-24f);
    const float detB = d0 * (d1*d2 - a12*a12)
                     - a01 * (a01*d2 - a12*a02)
                     + a02 * (a01*a12 - d1*a02);
    const float ip  = rsqrtf(p2);            // 1/p
    float r = 0.5f * detB * (ip * ip * ip);
    r = fminf(fmaxf(r, -1.0f), 1.0f);
    const float phi = acosf(r) * (1.0f / 3.0f);
    const float twop = 2.0f * p2 * ip;       // 2p
    const float l1 = qm + twop * __cosf(phi);                 // largest
    const float l3 = qm + twop * __cosf(phi + 2.0943951f);    // smallest
    const float l2 = 3.0f * qm - l1 - l3;

    // cancellation-free divided differences of f(x)=1/sqrt(x)
    const float u = sqrtf(l1), v = sqrtf(l2), w = sqrtf(l3);
    const float uv = u + v, vw = v + w, uw = u + w;
    const float rden = 1.0f / ((u * v * w) * uv * vw * uw);
    const float c2 = (u + v + w) * rden;
    const float c1 = -(w * vw * uw) * rden;
    const float c0 = (v * w) * (vw * uv * uw) * rden;   // = 1/u

    // S = c0*I + c1*(A-l1 I) + c2*(A-l1 I)(A-l2 I)
    const float e0 = a00 - l1, e1 = a11 - l1, e2 = a22 - l1;
    const float g0 = a00 - l2, g1 = a11 - l2, g2 = a22 - l2;
    const float P00 = e0*g0 + a01*a01 + a02*a02;
    const float P01 = a01*(e0 + g1) + a02*a12;
    const float P02 = a02*(e0 + g2) + a01*a12;
    const float P11 = a01*a01 + e1*g1 + a12*a12;
    const float P12 = a12*(e1 + g2) + a01*a02;
    const float P22 = a02*a02 + a12*a12 + e2*g2;

    const float S00 = fmaf(c2, P00, fmaf(c1, e0, c0));
    const float S01 = fmaf(c2, P01, c1 * a01);
    const float S02 = fmaf(c2, P02, c1 * a02);
    const float S11 = fmaf(c2, P11, fmaf(c1, e1, c0));
    const float S12 = fmaf(c2, P12, c1 * a12);
    const float S22 = fmaf(c2, P22, fmaf(c1, e2, c0));

    // bias b = -S*m folds the mean subtraction into the transform
    const float bb0 = -(S00*m0 + S01*m1 + S02*m2);
    const float bb1 = -(S01*m0 + S11*m1 + S12*m2);
    const float bb2 = -(S02*m0 + S12*m1 + S22*m2);

    // ---- epilogue: transform from registers + weight, streaming stores ----
    if (valid) {
        const float4* __restrict__ w4p = (const float4*)weight;
        float4* __restrict__ xout = (float4*)(out + sample * 768);

        #pragma unroll
        for (int c = 0; c < 2; c++) {
            float4 a = x[c], b = x[2 + c], d = x[4 + c];
            float4 wv = __ldg(&w4p[c * 32 + lane]);

            float4 o;
            o.x = fmaf(S00, a.x, fmaf(S01, b.x, fmaf(S02, d.x, bb0))) * wv.x;
            o.y = fmaf(S00, a.y, fmaf(S01, b.y, fmaf(S02, d.y, bb0))) * wv.y;
            o.z = fmaf(S00, a.z, fmaf(S01, b.z, fmaf(S02, d.z, bb0))) * wv.z;
            o.w = fmaf(S00, a.w, fmaf(S01, b.w, fmaf(S02, d.w, bb0))) * wv.w;
            __stcs(&xout[       c * 32 + lane], o);

            o.x = fmaf(S01, a.x, fmaf(S11, b.x, fmaf(S12, d.x, bb1))) * wv.x;
            o.y = fmaf(S01, a.y, fmaf(S11, b.y, fmaf(S12, d.y, bb1))) * wv.y;
            o.z = fmaf(S01, a.z, fmaf(S11, b.z, fmaf(S12, d.z, bb1))) * wv.z;
            o.w = fmaf(S01, a.w, fmaf(S11, b.w, fmaf(S12, d.w, bb1))) * wv.w;
            __stcs(&xout[ 64 +  c * 32 + lane], o);

            o.x = fmaf(S02, a.x, fmaf(S12, b.x, fmaf(S22, d.x, bb2))) * wv.x;
            o.y = fmaf(S02, a.y, fmaf(S12, b.y, fmaf(S22, d.y, bb2))) * wv.y;
            o.z = fmaf(S02, a.z, fmaf(S12, b.z, fmaf(S22, d.z, bb2))) * wv.z;
            o.w = fmaf(S02, a.w, fmaf(S12, b.w, fmaf(S22, d.w, bb2))) * wv.w;
            __stcs(&xout[128 +  c * 32 + lane], o);
        }
    }

    // note: x[1],x[3],x[5] pairs are used in epilogue as x[c],x[2+c],x[4+c]
    // with c in {0,1}: row0 = x[0],x[1]; row1 = x[2],x[3]; row2 = x[4],x[5].
}

extern "C" void kernel_launch(void* const* d_in, const int* in_sizes, int n_in,
                              void* d_out, int out_size)
{
    const float* in = (const float*)d_in[0];
    const float* w  = (const float*)d_in[1];
    float* out      = (float*)d_out;

    int nSamples = in_sizes[0] / 768;        // N*3*256 elements -> N samples
    int grid = (nSamples + 1) / 2;           // 2 samples per 64-thread block
    eqln_kernel<<<grid, 64>>>(in, w, out, nSamples);
}